// round 7
// baseline (speedup 1.0000x reference)
#include <cuda_runtime.h>
#include <cstdint>

// ---------------------------------------------------------------------------
// GNN message passing, 50000 nodes / 400000 edges / HIDDEN=256 / 3 layers.
// tf32 mma.sync.m16n8k8 GEMMs, cp.async pipelines, cvt hoisted out of loops.
// NEW: fused message kernel — hidden1 (gather + small MLP) computed straight
// into smem, consumed by the 128x256x256 edge GEMM in the same CTA, scatter
// via red.global.add.v2. M1 never touches DRAM.
// ---------------------------------------------------------------------------

#define NN 50000
#define NE 400000

__device__ float g_Hcat[(size_t)NN * 512];   // [h | aggr], h tf32-rounded
__device__ float g_P[(size_t)NN * 512];      // [Pa | Pb] (fp32)
__device__ float g_U[(size_t)NN * 256];      // update hidden, tf32-rounded
__device__ float g_E[(size_t)NE * 32];       // projected edge features
__device__ float g_T[(size_t)NN * 128];      // token head hidden
__device__ float g_Xc[(size_t)NN * 128];     // x, tf32-rounded
__device__ float g_Wc[1269760];              // all weights, tf32-rounded

#define WC_MSG1 0                            // 3*544*256
#define WC_MSG2 417792                       // 3*256*256
#define WC_UP1  614400                       // 3*512*256
#define WC_UP2  1007616                      // 3*256*256
#define WC_NODE 1204224                      // 128*256
#define WC_TOK  1236992                      // 256*128

__device__ __forceinline__ unsigned f2tf(float f) {
    unsigned u;
    asm("cvt.rna.tf32.f32 %0, %1;" : "=r"(u) : "f"(f));
    return u;
}
__device__ __forceinline__ float f2tf_f(float f) {
    return __uint_as_float(f2tf(f));
}
__device__ __forceinline__ uint32_t smem_u32(const void* p) {
    return (uint32_t)__cvta_generic_to_shared(p);
}
__device__ __forceinline__ void cp16(uint32_t dst, const void* src) {
    asm volatile("cp.async.cg.shared.global [%0], [%1], 16;" :: "r"(dst), "l"(src));
}
__device__ __forceinline__ void cp_commit() {
    asm volatile("cp.async.commit_group;" ::: "memory");
}

// ======================= generic node-side GEMM ============================
#define AW 20
#define ABUF 2560
#define BW 136
#define BBUF 2176
#define BOFF 7680
#define BIASOFF 14208
#define SMEM_BYTES ((BIASOFF + 128) * 4)

template <bool RELU, bool SCATTER, bool PRECVT, bool RSTORE>
__global__ __launch_bounds__(256, 2) void tf32gemm(
    const float* __restrict__ A, int lda,
    const float* __restrict__ B, int ldb,
    const float* __restrict__ bias,
    float* __restrict__ C, int ldc,
    int M, int K,
    const int* __restrict__ sidx)
{
    extern __shared__ unsigned dynsmem[];

    const int tid  = threadIdx.x;
    const int lane = tid & 31;
    const int wid  = tid >> 5;
    const int warpRow = wid >> 1;
    const int warpCol = wid & 1;
    const int qr = lane >> 2;
    const int qk = lane & 3;

    const int row0 = blockIdx.y * 128;
    const int col0 = blockIdx.x * 128;

    const int aRow = tid >> 2;
    const int aC4  = tid & 3;
    const int bK   = tid >> 5;
    const int bC4  = tid & 31;

    float* sbias = (float*)(dynsmem + BIASOFF);
    if (tid < 128) sbias[tid] = bias ? bias[col0 + tid] : 0.f;

    const int nc = K >> 4;

    auto cpA = [&](int s, int k0) {
        unsigned* buf = dynsmem + (s % 3) * ABUF;
#pragma unroll
        for (int u = 0; u < 2; u++) {
            int row = aRow + u * 64;
            int gr = min(row0 + row, M - 1);
            cp16(smem_u32(&buf[row * AW + aC4 * 4]),
                 A + (size_t)gr * lda + k0 + aC4 * 4);
        }
    };
    auto cpB = [&](int s, int k0) {
        unsigned* buf = dynsmem + BOFF + (s % 3) * BBUF;
#pragma unroll
        for (int u = 0; u < 2; u++) {
            int k = bK + u * 8;
            cp16(smem_u32(&buf[k * BW + bC4 * 4]),
                 B + (size_t)(k0 + k) * ldb + col0 + bC4 * 4);
        }
    };
    float4 aReg[2];
    auto ldgA = [&](int k0) {
#pragma unroll
        for (int u = 0; u < 2; u++) {
            int row = aRow + u * 64;
            if (row0 + row < M)
                aReg[u] = *(const float4*)(A + (size_t)(row0 + row) * lda + k0 + aC4 * 4);
            else
                aReg[u] = make_float4(0.f, 0.f, 0.f, 0.f);
        }
    };
    auto stsA = [&](int s) {
        unsigned* buf = dynsmem + (s % 3) * ABUF;
#pragma unroll
        for (int u = 0; u < 2; u++) {
            int row = aRow + u * 64;
            uint4 w = { f2tf(aReg[u].x), f2tf(aReg[u].y),
                        f2tf(aReg[u].z), f2tf(aReg[u].w) };
            *(uint4*)&buf[row * AW + aC4 * 4] = w;
        }
    };

    if (PRECVT) {
        cpA(0, 0);  cpB(0, 0);  cp_commit();
        cpA(1, 16); cpB(1, 16); cp_commit();
    } else {
        ldgA(0); stsA(0);
        cpB(0, 0);  cp_commit();
        cpB(1, 16); cp_commit();
    }

    float acc[2][8][4];
#pragma unroll
    for (int i = 0; i < 2; i++)
#pragma unroll
        for (int j = 0; j < 8; j++)
#pragma unroll
            for (int c = 0; c < 4; c++) acc[i][j][c] = 0.f;

    const int mbase = warpRow * 32;
    const int nbase = warpCol * 64;

    for (int s = 0; s < nc; s++) {
        if (!PRECVT && s + 1 < nc) ldgA((s + 1) << 4);

        if (s + 1 < nc)
            asm volatile("cp.async.wait_group 1;" ::: "memory");
        else
            asm volatile("cp.async.wait_group 0;" ::: "memory");
        __syncthreads();

        if (s + 2 < nc) {
            if (PRECVT) cpA(s + 2, (s + 2) << 4);
            cpB(s + 2, (s + 2) << 4);
            cp_commit();
        }

        const unsigned* As = dynsmem + (s % 3) * ABUF;
        const unsigned* Bs = dynsmem + BOFF + (s % 3) * BBUF;

#pragma unroll
        for (int kk = 0; kk < 16; kk += 8) {
            unsigned a[2][4], b[8][2];
#pragma unroll
            for (int i = 0; i < 2; i++) {
                int r = mbase + i * 16 + qr;
                a[i][0] = As[r * AW + kk + qk];
                a[i][1] = As[(r + 8) * AW + kk + qk];
                a[i][2] = As[r * AW + kk + 4 + qk];
                a[i][3] = As[(r + 8) * AW + kk + 4 + qk];
            }
#pragma unroll
            for (int j = 0; j < 8; j++) {
                int c = nbase + j * 8 + qr;
                b[j][0] = Bs[(kk + qk) * BW + c];
                b[j][1] = Bs[(kk + 4 + qk) * BW + c];
            }
#pragma unroll
            for (int i = 0; i < 2; i++)
#pragma unroll
                for (int j = 0; j < 8; j++) {
                    asm volatile(
                        "mma.sync.aligned.m16n8k8.row.col.f32.tf32.tf32.f32 "
                        "{%0,%1,%2,%3}, {%4,%5,%6,%7}, {%8,%9}, {%0,%1,%2,%3};"
                        : "+f"(acc[i][j][0]), "+f"(acc[i][j][1]),
                          "+f"(acc[i][j][2]), "+f"(acc[i][j][3])
                        : "r"(a[i][0]), "r"(a[i][1]), "r"(a[i][2]), "r"(a[i][3]),
                          "r"(b[j][0]), "r"(b[j][1]));
                }
        }

        if (!PRECVT && s + 1 < nc) stsA(s + 1);
    }

#pragma unroll
    for (int i = 0; i < 2; i++) {
#pragma unroll
        for (int h = 0; h < 2; h++) {
            int r = row0 + mbase + i * 16 + qr + h * 8;
            if (r >= M) continue;
            if (SCATTER) {
                int target = sidx[r];
                float* Crow = C + (size_t)target * ldc;
#pragma unroll
                for (int j = 0; j < 8; j++) {
                    int c = col0 + nbase + j * 8 + 2 * qk;
                    float v0 = acc[i][j][h * 2 + 0] + sbias[c - col0];
                    float v1 = acc[i][j][h * 2 + 1] + sbias[c - col0 + 1];
                    if (RELU) { v0 = fmaxf(v0, 0.f); v1 = fmaxf(v1, 0.f); }
                    asm volatile("red.global.add.v2.f32 [%0], {%1, %2};"
                                 :: "l"(Crow + c), "f"(v0), "f"(v1) : "memory");
                }
            } else {
                float* Crow = C + (size_t)r * ldc;
#pragma unroll
                for (int j = 0; j < 8; j++) {
                    int c = col0 + nbase + j * 8 + 2 * qk;
                    float v0 = acc[i][j][h * 2 + 0] + sbias[c - col0];
                    float v1 = acc[i][j][h * 2 + 1] + sbias[c - col0 + 1];
                    if (RELU) { v0 = fmaxf(v0, 0.f); v1 = fmaxf(v1, 0.f); }
                    if (RSTORE) { v0 = f2tf_f(v0); v1 = f2tf_f(v1); }
                    *(float2*)(Crow + c) = make_float2(v0, v1);
                }
            }
        }
    }
}

// ======================= fused message kernel ==============================
// Tile: 128 edges x 256 cols, 512 threads, 1 CTA/SM.
// Phase 1: H1[i][j] = rna(relu(b1[j] + Pa[dst][j] + Pb[src][j] + e[i]·Wc[:,j]))
//          -> smem (stride 260, conflict-free for STS and mma a-frags)
// Phase 2: aggr[dst] += relu(H1 @ W2 + b2)  (tf32 mma, 2-stage cp.async B,
//          red.global.add.v2 scatter).  Requires E % 128 == 0.
// smem words: H1 33280 | Bs 2*4224 @33280 | esm 4096 @41728 |
//             sbias 256 @45824 | sdst 128 @46080 | ssrc 128 @46208
#define MK_H1     0
#define MK_BS     33280
#define MK_ESM    41728
#define MK_BIAS   45824
#define MK_DST    46080
#define MK_SRC    46208
#define MK_WORDS  46336
#define MK_SMEM_BYTES (MK_WORDS * 4)
#define H1W 260
#define MBW 264

__global__ __launch_bounds__(512, 1) void msg_fused(
    const float* __restrict__ P,     // [N, 512] = [Pa | Pb] fp32
    const float* __restrict__ Ebuf,  // [E, 32]
    const float* __restrict__ Wc,    // msg_w1[l] + 512*256 (fp32 [32][256])
    const float* __restrict__ b1,    // [256]
    const float* __restrict__ W2c,   // msg_w2[l] tf32-rounded [256][256]
    const float* __restrict__ b2,    // [256]
    const int* __restrict__ src,
    const int* __restrict__ dst,
    float* __restrict__ Caggr,       // Hcat + 256, ldc = 512
    int E)
{
    extern __shared__ unsigned sm[];
    unsigned* H1   = sm + MK_H1;
    unsigned* Bs   = sm + MK_BS;
    float*  esm    = (float*)(sm + MK_ESM);
    float*  sbias  = (float*)(sm + MK_BIAS);
    int*    sdst   = (int*)(sm + MK_DST);
    int*    ssrc   = (int*)(sm + MK_SRC);

    const int tid  = threadIdx.x;
    const int e0   = blockIdx.x * 128;

    // ---- load indices / edge tile / bias ----
    if (tid < 128) sdst[tid] = dst[e0 + tid];
    else if (tid < 256) ssrc[tid - 128] = src[e0 + (tid - 128)];
    else if (tid < 512) sbias[tid - 256] = b2[tid - 256];
    {
        const float4* esrc = (const float4*)(Ebuf + (size_t)e0 * 32);
        float4* edst4 = (float4*)esm;
        for (int t = tid; t < 1024; t += 512) edst4[t] = esrc[t];
    }

    // B chunk staging helper (16 rows x 256 cols per chunk)
    const int bRow = tid >> 6;          // 0..7 (+8)
    const int bC4  = tid & 63;          // 0..63
    auto cpB = [&](int s, int k0) {
        unsigned* buf = Bs + (s & 1) * 4224;
#pragma unroll
        for (int u = 0; u < 2; u++) {
            int k = bRow + u * 8;
            cp16(smem_u32(&buf[k * MBW + bC4 * 4]),
                 W2c + (size_t)(k0 + k) * 256 + bC4 * 4);
        }
    };
    // prefetch B chunks 0,1 during phase 1
    cpB(0, 0);  cp_commit();
    cpB(1, 16); cp_commit();

    __syncthreads();

    // ---- phase 1: hidden1 into smem ----
    {
        const int j    = tid & 255;
        const int half = tid >> 8;
        float wc[32];
#pragma unroll
        for (int k = 0; k < 32; k++) wc[k] = Wc[k * 256 + j];
        const float bj = b1[j];
        const int i0 = half * 64;
#pragma unroll 4
        for (int i = i0; i < i0 + 64; i++) {
            float acc = bj + P[(size_t)sdst[i] * 512 + j]
                           + P[(size_t)ssrc[i] * 512 + 256 + j];
#pragma unroll
            for (int k = 0; k < 32; k++) acc = fmaf(esm[i * 32 + k], wc[k], acc);
            H1[i * H1W + j] = f2tf(fmaxf(acc, 0.f));
        }
    }
    __syncthreads();

    // ---- phase 2: 128x256x256 GEMM + scatter ----
    const int lane = tid & 31;
    const int wid  = tid >> 5;
    const int warpRow = wid >> 2;       // 0..3
    const int warpCol = wid & 3;        // 0..3
    const int qr = lane >> 2;
    const int qk = lane & 3;
    const int mbase = warpRow * 32;
    const int nbase = warpCol * 64;

    float acc[2][8][4];
#pragma unroll
    for (int i = 0; i < 2; i++)
#pragma unroll
        for (int j = 0; j < 8; j++)
#pragma unroll
            for (int c = 0; c < 4; c++) acc[i][j][c] = 0.f;

    for (int s = 0; s < 16; s++) {
        if (s + 1 < 16)
            asm volatile("cp.async.wait_group 1;" ::: "memory");
        else
            asm volatile("cp.async.wait_group 0;" ::: "memory");
        __syncthreads();

        const unsigned* Bcur = Bs + (s & 1) * 4224;
        const int koff = s * 16;

#pragma unroll
        for (int kk = 0; kk < 16; kk += 8) {
            unsigned a[2][4], b[8][2];
#pragma unroll
            for (int i = 0; i < 2; i++) {
                int r = mbase + i * 16 + qr;
                a[i][0] = H1[r * H1W + koff + kk + qk];
                a[i][1] = H1[(r + 8) * H1W + koff + kk + qk];
                a[i][2] = H1[r * H1W + koff + kk + 4 + qk];
                a[i][3] = H1[(r + 8) * H1W + koff + kk + 4 + qk];
            }
#pragma unroll
            for (int j = 0; j < 8; j++) {
                int c = nbase + j * 8 + qr;
                b[j][0] = Bcur[(kk + qk) * MBW + c];
                b[j][1] = Bcur[(kk + 4 + qk) * MBW + c];
            }
#pragma unroll
            for (int i = 0; i < 2; i++)
#pragma unroll
                for (int j = 0; j < 8; j++) {
                    asm volatile(
                        "mma.sync.aligned.m16n8k8.row.col.f32.tf32.tf32.f32 "
                        "{%0,%1,%2,%3}, {%4,%5,%6,%7}, {%8,%9}, {%0,%1,%2,%3};"
                        : "+f"(acc[i][j][0]), "+f"(acc[i][j][1]),
                          "+f"(acc[i][j][2]), "+f"(acc[i][j][3])
                        : "r"(a[i][0]), "r"(a[i][1]), "r"(a[i][2]), "r"(a[i][3]),
                          "r"(b[j][0]), "r"(b[j][1]));
                }
        }

        __syncthreads();
        if (s + 2 < 16) { cpB(s + 2, (s + 2) << 4); cp_commit(); }
    }

    // scatter epilogue
#pragma unroll
    for (int i = 0; i < 2; i++) {
#pragma unroll
        for (int h = 0; h < 2; h++) {
            int rl = mbase + i * 16 + qr + h * 8;     // 0..127, always valid
            int target = sdst[rl];
            float* Crow = Caggr + (size_t)target * 512;
#pragma unroll
            for (int j = 0; j < 8; j++) {
                int c = nbase + j * 8 + 2 * qk;
                float v0 = acc[i][j][h * 2 + 0] + sbias[c];
                float v1 = acc[i][j][h * 2 + 1] + sbias[c + 1];
                v0 = fmaxf(v0, 0.f); v1 = fmaxf(v1, 0.f);
                asm volatile("red.global.add.v2.f32 [%0], {%1, %2};"
                             :: "l"(Crow + c), "f"(v0), "f"(v1) : "memory");
            }
        }
    }
}

// ======================= small kernels =====================================
__global__ void cvt_buf(const float* __restrict__ src, float* __restrict__ dst, int n4)
{
    int i = blockIdx.x * blockDim.x + threadIdx.x;
    if (i < n4) {
        float4 v = *(const float4*)(src + i * 4);
        float4 o = { f2tf_f(v.x), f2tf_f(v.y), f2tf_f(v.z), f2tf_f(v.w) };
        *(float4*)(dst + i * 4) = o;
    }
}

__global__ __launch_bounds__(256) void edge_proj(
    const float* __restrict__ ea, const float* __restrict__ W,
    const float* __restrict__ b, float* __restrict__ out, int E)
{
    __shared__ float Ws[1024];
    __shared__ float es[8][32];
    const int t = threadIdx.x;
    for (int i = t; i < 1024; i += 256) Ws[i] = W[i];
    const int e0 = blockIdx.x * 8;
    const int ne = min(8, E - e0);
    for (int i = t; i < ne * 32; i += 256)
        es[i >> 5][i & 31] = ea[(size_t)e0 * 32 + i];
    __syncthreads();
    const int el = t >> 5, c = t & 31;
    if (el < ne) {
        float acc = b[c];
#pragma unroll
        for (int k = 0; k < 32; k++) acc = fmaf(es[el][k], Ws[k * 32 + c], acc);
        out[(size_t)(e0 + el) * 32 + c] = acc;
    }
}

__global__ void zero_aggr(float* __restrict__ Hcat, int N)
{
    int idx = blockIdx.x * blockDim.x + threadIdx.x;
    if (idx < N * 64) {
        int r = idx >> 6, c = (idx & 63) << 2;
        *(float4*)(Hcat + (size_t)r * 512 + 256 + c) = make_float4(0.f, 0.f, 0.f, 0.f);
    }
}

__global__ void head2(const float* __restrict__ T, const float* __restrict__ w2,
                      const float* __restrict__ b2, float* __restrict__ out, int N)
{
    int gw = (blockIdx.x * blockDim.x + threadIdx.x) >> 5;
    int lane = threadIdx.x & 31;
    if (gw >= N) return;
    const float* row = T + (size_t)gw * 128;
    float s = 0.f;
#pragma unroll
    for (int k = lane; k < 128; k += 32) s = fmaf(row[k], w2[k], s);
#pragma unroll
    for (int o = 16; o; o >>= 1) s += __shfl_xor_sync(0xFFFFFFFFu, s, o);
    if (lane == 0) out[gw] = s + b2[0];
}

__global__ void copy_h(const float* __restrict__ Hcat, float* __restrict__ out, int N)
{
    int idx = blockIdx.x * blockDim.x + threadIdx.x;
    if (idx < N * 64) {
        int r = idx >> 6, c = (idx & 63) << 2;
        *(float4*)(out + (size_t)r * 256 + c) =
            *(const float4*)(Hcat + (size_t)r * 512 + c);
    }
}

// ---------------------------------------------------------------------------
extern "C" void kernel_launch(void* const* d_in, const int* in_sizes, int n_in,
                              void* d_out, int out_size)
{
    const float* x       = (const float*)d_in[0];
    const int*   ei      = (const int*)d_in[1];
    const float* ea      = (const float*)d_in[2];
    const float* node_w  = (const float*)d_in[3];
    const float* node_b  = (const float*)d_in[4];
    const float* edge_w  = (const float*)d_in[5];
    const float* edge_b  = (const float*)d_in[6];
    const float* msg_w1  = (const float*)d_in[7];
    const float* msg_b1  = (const float*)d_in[8];
    const float* msg_w2  = (const float*)d_in[9];
    const float* msg_b2  = (const float*)d_in[10];
    const float* up_w1   = (const float*)d_in[11];
    const float* up_b1   = (const float*)d_in[12];
    const float* up_w2   = (const float*)d_in[13];
    const float* up_b2   = (const float*)d_in[14];
    const float* tok_w1  = (const float*)d_in[15];
    const float* tok_b1  = (const float*)d_in[16];
    const float* tok_w2  = (const float*)d_in[17];
    const float* tok_b2  = (const float*)d_in[18];

    const int N = in_sizes[0] / 128;   // 50000
    const int E = in_sizes[2] / 32;    // 400000
    const int* src = ei;
    const int* dst = ei + E;

    float *Hcat, *P, *U, *Eb, *T, *Xc, *Wc;
    cudaGetSymbolAddress((void**)&Hcat, g_Hcat);
    cudaGetSymbolAddress((void**)&P,    g_P);
    cudaGetSymbolAddress((void**)&U,    g_U);
    cudaGetSymbolAddress((void**)&Eb,   g_E);
    cudaGetSymbolAddress((void**)&T,    g_T);
    cudaGetSymbolAddress((void**)&Xc,   g_Xc);
    cudaGetSymbolAddress((void**)&Wc,   g_Wc);

    float* out_logits = (float*)d_out;
    float* out_h      = out_logits + N;

    const int mbN = (N + 127) / 128;   // 391

    cudaFuncSetAttribute(tf32gemm<false, false, true,  true >, cudaFuncAttributeMaxDynamicSharedMemorySize, SMEM_BYTES);
    cudaFuncSetAttribute(tf32gemm<false, false, true,  false>, cudaFuncAttributeMaxDynamicSharedMemorySize, SMEM_BYTES);
    cudaFuncSetAttribute(tf32gemm<true,  false, false, true >, cudaFuncAttributeMaxDynamicSharedMemorySize, SMEM_BYTES);
    cudaFuncSetAttribute(tf32gemm<true,  false, true,  true >, cudaFuncAttributeMaxDynamicSharedMemorySize, SMEM_BYTES);
    cudaFuncSetAttribute(tf32gemm<true,  false, true,  false>, cudaFuncAttributeMaxDynamicSharedMemorySize, SMEM_BYTES);
    cudaFuncSetAttribute(msg_fused, cudaFuncAttributeMaxDynamicSharedMemorySize, MK_SMEM_BYTES);

    // ---- pre-convert weights + x to tf32 ----
    cvt_buf<<<(3 * 544 * 256 / 4 + 255) / 256, 256>>>(msg_w1, Wc + WC_MSG1, 3 * 544 * 256 / 4);
    cvt_buf<<<(3 * 256 * 256 / 4 + 255) / 256, 256>>>(msg_w2, Wc + WC_MSG2, 3 * 256 * 256 / 4);
    cvt_buf<<<(3 * 512 * 256 / 4 + 255) / 256, 256>>>(up_w1,  Wc + WC_UP1,  3 * 512 * 256 / 4);
    cvt_buf<<<(3 * 256 * 256 / 4 + 255) / 256, 256>>>(up_w2,  Wc + WC_UP2,  3 * 256 * 256 / 4);
    cvt_buf<<<(128 * 256 / 4 + 255) / 256, 256>>>(node_w, Wc + WC_NODE, 128 * 256 / 4);
    cvt_buf<<<(256 * 128 / 4 + 255) / 256, 256>>>(tok_w1, Wc + WC_TOK,  256 * 128 / 4);
    cvt_buf<<<(NN * 128 / 4 + 255) / 256, 256>>>(x, Xc, NN * 128 / 4);

    // h = x @ node_w + node_b -> Hcat[:, 0:256]
    tf32gemm<false, false, true, true><<<dim3(2, mbN), 256, SMEM_BYTES>>>(
        Xc, 128, Wc + WC_NODE, 256, node_b, Hcat, 512, N, 128, nullptr);
    // e = edge_attr @ edge_w + edge_b
    edge_proj<<<(E + 7) / 8, 256>>>(ea, edge_w, edge_b, Eb, E);

    for (int l = 0; l < 3; l++) {
        const float* w1c = Wc + WC_MSG1 + (size_t)l * 544 * 256;
        // Pa, Pb
        tf32gemm<false, false, true, false><<<dim3(2, mbN), 256, SMEM_BYTES>>>(
            Hcat, 512, w1c, 256, nullptr, P, 512, N, 256, nullptr);
        tf32gemm<false, false, true, false><<<dim3(2, mbN), 256, SMEM_BYTES>>>(
            Hcat, 512, w1c + 256 * 256, 256, nullptr, P + 256, 512, N, 256, nullptr);
        // aggr = 0
        zero_aggr<<<(N * 64 + 255) / 256, 256>>>(Hcat, N);
        // fused message MLP + scatter
        msg_fused<<<E / 128, 512, MK_SMEM_BYTES>>>(
            P, Eb,
            msg_w1 + (size_t)l * 544 * 256 + 512 * 256, msg_b1 + l * 256,
            Wc + WC_MSG2 + (size_t)l * 256 * 256, msg_b2 + l * 256,
            src, dst, Hcat + 256, E);
        // u = relu([h|aggr] @ up_w1 + b1)
        tf32gemm<true, false, false, true><<<dim3(2, mbN), 256, SMEM_BYTES>>>(
            Hcat, 512, Wc + WC_UP1 + (size_t)l * 512 * 256, 256,
            up_b1 + l * 256, U, 256, N, 512, nullptr);
        // h = relu(u @ up_w2 + b2)
        tf32gemm<true, false, true, true><<<dim3(2, mbN), 256, SMEM_BYTES>>>(
            U, 256, Wc + WC_UP2 + (size_t)l * 256 * 256, 256,
            up_b2 + l * 256, Hcat, 512, N, 256, nullptr);
    }

    // token head
    tf32gemm<true, false, true, false><<<dim3(1, mbN), 256, SMEM_BYTES>>>(
        Hcat, 512, Wc + WC_TOK, 128, tok_b1, T, 128, N, 256, nullptr);
    head2<<<(N * 32 + 255) / 256, 256>>>(T, tok_w2, tok_b2, out_logits, N);
    copy_h<<<(N * 64 + 255) / 256, 256>>>(Hcat, out_h, N);
}

// round 8
// speedup vs baseline: 1.2190x; 1.2190x over previous
#include <cuda_runtime.h>
#include <cstdint>

// ---------------------------------------------------------------------------
// GNN message passing, 50000 nodes / 400000 edges / HIDDEN=256 / 3 layers.
// tf32 mma.sync.m16n8k8 GEMMs, cp.async 3-stage pipelines, cvt hoisted.
// R6 structure restored (fused msg kernel regressed). New: Pa|Pb merged into
// one N=512 GEMM via repacked Wab; all preamble cvt in one kernel.
// ---------------------------------------------------------------------------

#define NN 50000
#define NE 400000

__device__ float g_Hcat[(size_t)NN * 512];   // [h | aggr], h tf32-rounded
__device__ float g_P[(size_t)NN * 512];      // [Pa | Pb] (fp32)
__device__ float g_M1[(size_t)NE * 256];     // hidden1 per edge, tf32-rounded
__device__ float g_U[(size_t)NN * 256];      // update hidden, tf32-rounded
__device__ float g_E[(size_t)NE * 32];       // projected edge features
__device__ float g_T[(size_t)NN * 128];      // token head hidden
__device__ float g_Xc[(size_t)NN * 128];     // x, tf32-rounded
__device__ float g_Wc[1245184];              // all weights, tf32-rounded

// g_Wc offsets (floats)
#define WC_MSGAB 0                           // 3*256*512 = 393216 (repacked W1ab)
#define WC_MSG2  393216                      // 3*256*256 = 196608
#define WC_UP1   589824                      // 3*512*256 = 393216
#define WC_UP2   983040                      // 3*256*256 = 196608
#define WC_NODE  1179648                     // 128*256   = 32768
#define WC_TOK   1212416                     // 256*128   = 32768

__device__ __forceinline__ unsigned f2tf(float f) {
    unsigned u;
    asm("cvt.rna.tf32.f32 %0, %1;" : "=r"(u) : "f"(f));
    return u;
}
__device__ __forceinline__ float f2tf_f(float f) {
    return __uint_as_float(f2tf(f));
}
__device__ __forceinline__ uint32_t smem_u32(const void* p) {
    return (uint32_t)__cvta_generic_to_shared(p);
}
__device__ __forceinline__ void cp16(uint32_t dst, const void* src) {
    asm volatile("cp.async.cg.shared.global [%0], [%1], 16;" :: "r"(dst), "l"(src));
}
__device__ __forceinline__ void cp_commit() {
    asm volatile("cp.async.commit_group;" ::: "memory");
}

// smem layout (words): A bufs 3*2560 @0, B bufs 3*2176 @7680, bias 128 @14208
#define AW 20
#define ABUF 2560
#define BW 136
#define BBUF 2176
#define BOFF 7680
#define BIASOFF 14208
#define SMEM_BYTES ((BIASOFF + 128) * 4)

// ---------------------------------------------------------------------------
// TF32 GEMM: C[M, gridDim.x*128] = act(A[M,K] @ B[K,N] + bias)
// 128x128 CTA tile, BK=16, 256 threads (8 warps, 32x64 each), 3-stage cp.async.
// ---------------------------------------------------------------------------
template <bool RELU, bool SCATTER, bool PRECVT, bool RSTORE>
__global__ __launch_bounds__(256, 2) void tf32gemm(
    const float* __restrict__ A, int lda,
    const float* __restrict__ B, int ldb,
    const float* __restrict__ bias,
    float* __restrict__ C, int ldc,
    int M, int K,
    const int* __restrict__ sidx)
{
    extern __shared__ unsigned dynsmem[];

    const int tid  = threadIdx.x;
    const int lane = tid & 31;
    const int wid  = tid >> 5;
    const int warpRow = wid >> 1;
    const int warpCol = wid & 1;
    const int qr = lane >> 2;
    const int qk = lane & 3;

    const int row0 = blockIdx.y * 128;
    const int col0 = blockIdx.x * 128;

    const int aRow = tid >> 2;
    const int aC4  = tid & 3;
    const int bK   = tid >> 5;
    const int bC4  = tid & 31;

    float* sbias = (float*)(dynsmem + BIASOFF);
    if (tid < 128) sbias[tid] = bias ? bias[col0 + tid] : 0.f;

    const int nc = K >> 4;

    auto cpA = [&](int s, int k0) {
        unsigned* buf = dynsmem + (s % 3) * ABUF;
#pragma unroll
        for (int u = 0; u < 2; u++) {
            int row = aRow + u * 64;
            int gr = min(row0 + row, M - 1);
            cp16(smem_u32(&buf[row * AW + aC4 * 4]),
                 A + (size_t)gr * lda + k0 + aC4 * 4);
        }
    };
    auto cpB = [&](int s, int k0) {
        unsigned* buf = dynsmem + BOFF + (s % 3) * BBUF;
#pragma unroll
        for (int u = 0; u < 2; u++) {
            int k = bK + u * 8;
            cp16(smem_u32(&buf[k * BW + bC4 * 4]),
                 B + (size_t)(k0 + k) * ldb + col0 + bC4 * 4);
        }
    };
    float4 aReg[2];
    auto ldgA = [&](int k0) {
#pragma unroll
        for (int u = 0; u < 2; u++) {
            int row = aRow + u * 64;
            if (row0 + row < M)
                aReg[u] = *(const float4*)(A + (size_t)(row0 + row) * lda + k0 + aC4 * 4);
            else
                aReg[u] = make_float4(0.f, 0.f, 0.f, 0.f);
        }
    };
    auto stsA = [&](int s) {
        unsigned* buf = dynsmem + (s % 3) * ABUF;
#pragma unroll
        for (int u = 0; u < 2; u++) {
            int row = aRow + u * 64;
            uint4 w = { f2tf(aReg[u].x), f2tf(aReg[u].y),
                        f2tf(aReg[u].z), f2tf(aReg[u].w) };
            *(uint4*)&buf[row * AW + aC4 * 4] = w;
        }
    };

    if (PRECVT) {
        cpA(0, 0);  cpB(0, 0);  cp_commit();
        cpA(1, 16); cpB(1, 16); cp_commit();
    } else {
        ldgA(0); stsA(0);
        cpB(0, 0);  cp_commit();
        cpB(1, 16); cp_commit();
    }

    float acc[2][8][4];
#pragma unroll
    for (int i = 0; i < 2; i++)
#pragma unroll
        for (int j = 0; j < 8; j++)
#pragma unroll
            for (int c = 0; c < 4; c++) acc[i][j][c] = 0.f;

    const int mbase = warpRow * 32;
    const int nbase = warpCol * 64;

    for (int s = 0; s < nc; s++) {
        if (!PRECVT && s + 1 < nc) ldgA((s + 1) << 4);

        if (s + 1 < nc)
            asm volatile("cp.async.wait_group 1;" ::: "memory");
        else
            asm volatile("cp.async.wait_group 0;" ::: "memory");
        __syncthreads();

        if (s + 2 < nc) {
            if (PRECVT) cpA(s + 2, (s + 2) << 4);
            cpB(s + 2, (s + 2) << 4);
            cp_commit();
        }

        const unsigned* As = dynsmem + (s % 3) * ABUF;
        const unsigned* Bs = dynsmem + BOFF + (s % 3) * BBUF;

#pragma unroll
        for (int kk = 0; kk < 16; kk += 8) {
            unsigned a[2][4], b[8][2];
#pragma unroll
            for (int i = 0; i < 2; i++) {
                int r = mbase + i * 16 + qr;
                a[i][0] = As[r * AW + kk + qk];
                a[i][1] = As[(r + 8) * AW + kk + qk];
                a[i][2] = As[r * AW + kk + 4 + qk];
                a[i][3] = As[(r + 8) * AW + kk + 4 + qk];
            }
#pragma unroll
            for (int j = 0; j < 8; j++) {
                int c = nbase + j * 8 + qr;
                b[j][0] = Bs[(kk + qk) * BW + c];
                b[j][1] = Bs[(kk + 4 + qk) * BW + c];
            }
#pragma unroll
            for (int i = 0; i < 2; i++)
#pragma unroll
                for (int j = 0; j < 8; j++) {
                    asm volatile(
                        "mma.sync.aligned.m16n8k8.row.col.f32.tf32.tf32.f32 "
                        "{%0,%1,%2,%3}, {%4,%5,%6,%7}, {%8,%9}, {%0,%1,%2,%3};"
                        : "+f"(acc[i][j][0]), "+f"(acc[i][j][1]),
                          "+f"(acc[i][j][2]), "+f"(acc[i][j][3])
                        : "r"(a[i][0]), "r"(a[i][1]), "r"(a[i][2]), "r"(a[i][3]),
                          "r"(b[j][0]), "r"(b[j][1]));
                }
        }

        if (!PRECVT && s + 1 < nc) stsA(s + 1);
    }

#pragma unroll
    for (int i = 0; i < 2; i++) {
#pragma unroll
        for (int h = 0; h < 2; h++) {
            int r = row0 + mbase + i * 16 + qr + h * 8;
            if (r >= M) continue;
            if (SCATTER) {
                int target = sidx[r];
                float* Crow = C + (size_t)target * ldc;
#pragma unroll
                for (int j = 0; j < 8; j++) {
                    int c = col0 + nbase + j * 8 + 2 * qk;
                    float v0 = acc[i][j][h * 2 + 0] + sbias[c - col0];
                    float v1 = acc[i][j][h * 2 + 1] + sbias[c - col0 + 1];
                    if (RELU) { v0 = fmaxf(v0, 0.f); v1 = fmaxf(v1, 0.f); }
                    asm volatile("red.global.add.v2.f32 [%0], {%1, %2};"
                                 :: "l"(Crow + c), "f"(v0), "f"(v1) : "memory");
                }
            } else {
                float* Crow = C + (size_t)r * ldc;
#pragma unroll
                for (int j = 0; j < 8; j++) {
                    int c = col0 + nbase + j * 8 + 2 * qk;
                    float v0 = acc[i][j][h * 2 + 0] + sbias[c - col0];
                    float v1 = acc[i][j][h * 2 + 1] + sbias[c - col0 + 1];
                    if (RELU) { v0 = fmaxf(v0, 0.f); v1 = fmaxf(v1, 0.f); }
                    if (RSTORE) { v0 = f2tf_f(v0); v1 = f2tf_f(v1); }
                    *(float2*)(Crow + c) = make_float2(v0, v1);
                }
            }
        }
    }
}

// ---------------------------------------------------------------------------
// One-shot preamble: tf32-round all weights + x; repack msg_w1[0:512] into
// Wab[256][512] (Wab[k][n<256]=W1[k][n], Wab[k][n>=256]=W1[256+k][n-256]).
// Segment dispatch on blockIdx.x; every segment is an exact multiple of
// 256 float4s per block.
// ---------------------------------------------------------------------------
__global__ __launch_bounds__(256) void cvt_all(
    const float* __restrict__ msg_w1, const float* __restrict__ msg_w2,
    const float* __restrict__ up_w1,  const float* __restrict__ up_w2,
    const float* __restrict__ node_w, const float* __restrict__ tok_w1,
    const float* __restrict__ x,
    float* __restrict__ Wc, float* __restrict__ Xc)
{
    const int b = blockIdx.x;
    const int t = threadIdx.x;
    const float* src;
    float* dst;
    int i4;
    if (b < 384) {                       // repack Wab: 3*256*512/4 = 98304 f4
        i4 = b * 256 + t;
        int l   = i4 >> 15;              // / 32768
        int rem = i4 & 32767;
        int k   = rem >> 7;
        int n   = (rem & 127) << 2;
        src = (n < 256)
            ? msg_w1 + (size_t)l * 544 * 256 + (size_t)k * 256 + n
            : msg_w1 + (size_t)l * 544 * 256 + (size_t)(256 + k) * 256 + (n - 256);
        dst = Wc + WC_MSGAB + (size_t)i4 * 4;
    } else if (b < 576) {                // msg_w2: 49152 f4
        i4 = (b - 384) * 256 + t;
        src = msg_w2 + (size_t)i4 * 4; dst = Wc + WC_MSG2 + (size_t)i4 * 4;
    } else if (b < 960) {                // up_w1: 98304 f4
        i4 = (b - 576) * 256 + t;
        src = up_w1 + (size_t)i4 * 4;  dst = Wc + WC_UP1 + (size_t)i4 * 4;
    } else if (b < 1152) {               // up_w2: 49152 f4
        i4 = (b - 960) * 256 + t;
        src = up_w2 + (size_t)i4 * 4;  dst = Wc + WC_UP2 + (size_t)i4 * 4;
    } else if (b < 1184) {               // node_w: 8192 f4
        i4 = (b - 1152) * 256 + t;
        src = node_w + (size_t)i4 * 4; dst = Wc + WC_NODE + (size_t)i4 * 4;
    } else if (b < 1216) {               // tok_w1: 8192 f4
        i4 = (b - 1184) * 256 + t;
        src = tok_w1 + (size_t)i4 * 4; dst = Wc + WC_TOK + (size_t)i4 * 4;
    } else {                             // x: 1600000 f4
        i4 = (b - 1216) * 256 + t;
        src = x + (size_t)i4 * 4;      dst = Xc + (size_t)i4 * 4;
    }
    float4 v = *(const float4*)src;
    float4 o = { f2tf_f(v.x), f2tf_f(v.y), f2tf_f(v.z), f2tf_f(v.w) };
    *(float4*)dst = o;
}
#define CVT_ALL_BLOCKS (1216 + 6250)

// ---------------------------------------------------------------------------
// hidden1[e, :] = rna(relu( Pa[dst[e]] + Pb[src[e]] + ebuf[e]·Wc + b1 ))
// ---------------------------------------------------------------------------
#define ET 16
__global__ __launch_bounds__(256) void hidden1_kernel(
    const float* __restrict__ P,    // [N, 512] = [Pa | Pb]
    const float* __restrict__ Ebuf, // [E, 32]
    const float* __restrict__ Wc,   // [32, 256] (original fp32)
    const float* __restrict__ b1,   // [256]
    const int* __restrict__ src,
    const int* __restrict__ dst,
    float* __restrict__ out,        // [E, 256] tf32-rounded
    int E)
{
    const int j = threadIdx.x;
    const int e0 = blockIdx.x * ET;
    __shared__ float esm[ET][32];
    __shared__ int sdst[ET], ssrc[ET];

    float wc[32];
#pragma unroll
    for (int k = 0; k < 32; k++) wc[k] = Wc[k * 256 + j];

    const int ne = min(ET, E - e0);
    if (j < ne) {
        sdst[j] = dst[e0 + j];
        ssrc[j] = src[e0 + j];
    }
    for (int t = j; t < ne * 32; t += 256)
        esm[t >> 5][t & 31] = Ebuf[(size_t)e0 * 32 + t];
    __syncthreads();

    const float bj = b1[j];
    for (int i = 0; i < ne; i++) {
        float acc = bj + P[(size_t)sdst[i] * 512 + j]
                       + P[(size_t)ssrc[i] * 512 + 256 + j];
#pragma unroll
        for (int k = 0; k < 32; k++) acc = fmaf(esm[i][k], wc[k], acc);
        out[(size_t)(e0 + i) * 256 + j] = f2tf_f(fmaxf(acc, 0.f));
    }
}

// ---------------------------------------------------------------------------
__global__ __launch_bounds__(256) void edge_proj(
    const float* __restrict__ ea, const float* __restrict__ W,
    const float* __restrict__ b, float* __restrict__ out, int E)
{
    __shared__ float Ws[1024];
    __shared__ float es[8][32];
    const int t = threadIdx.x;
    for (int i = t; i < 1024; i += 256) Ws[i] = W[i];
    const int e0 = blockIdx.x * 8;
    const int ne = min(8, E - e0);
    for (int i = t; i < ne * 32; i += 256)
        es[i >> 5][i & 31] = ea[(size_t)e0 * 32 + i];
    __syncthreads();
    const int el = t >> 5, c = t & 31;
    if (el < ne) {
        float acc = b[c];
#pragma unroll
        for (int k = 0; k < 32; k++) acc = fmaf(es[el][k], Ws[k * 32 + c], acc);
        out[(size_t)(e0 + el) * 32 + c] = acc;
    }
}

__global__ void zero_aggr(float* __restrict__ Hcat, int N)
{
    int idx = blockIdx.x * blockDim.x + threadIdx.x;
    if (idx < N * 64) {
        int r = idx >> 6, c = (idx & 63) << 2;
        *(float4*)(Hcat + (size_t)r * 512 + 256 + c) = make_float4(0.f, 0.f, 0.f, 0.f);
    }
}

__global__ void head2(const float* __restrict__ T, const float* __restrict__ w2,
                      const float* __restrict__ b2, float* __restrict__ out, int N)
{
    int gw = (blockIdx.x * blockDim.x + threadIdx.x) >> 5;
    int lane = threadIdx.x & 31;
    if (gw >= N) return;
    const float* row = T + (size_t)gw * 128;
    float s = 0.f;
#pragma unroll
    for (int k = lane; k < 128; k += 32) s = fmaf(row[k], w2[k], s);
#pragma unroll
    for (int o = 16; o; o >>= 1) s += __shfl_xor_sync(0xFFFFFFFFu, s, o);
    if (lane == 0) out[gw] = s + b2[0];
}

__global__ void copy_h(const float* __restrict__ Hcat, float* __restrict__ out, int N)
{
    int idx = blockIdx.x * blockDim.x + threadIdx.x;
    if (idx < N * 64) {
        int r = idx >> 6, c = (idx & 63) << 2;
        *(float4*)(out + (size_t)r * 256 + c) =
            *(const float4*)(Hcat + (size_t)r * 512 + c);
    }
}

// ---------------------------------------------------------------------------
extern "C" void kernel_launch(void* const* d_in, const int* in_sizes, int n_in,
                              void* d_out, int out_size)
{
    const float* x       = (const float*)d_in[0];
    const int*   ei      = (const int*)d_in[1];
    const float* ea      = (const float*)d_in[2];
    const float* node_w  = (const float*)d_in[3];
    const float* node_b  = (const float*)d_in[4];
    const float* edge_w  = (const float*)d_in[5];
    const float* edge_b  = (const float*)d_in[6];
    const float* msg_w1  = (const float*)d_in[7];
    const float* msg_b1  = (const float*)d_in[8];
    const float* msg_w2  = (const float*)d_in[9];
    const float* msg_b2  = (const float*)d_in[10];
    const float* up_w1   = (const float*)d_in[11];
    const float* up_b1   = (const float*)d_in[12];
    const float* up_w2   = (const float*)d_in[13];
    const float* up_b2   = (const float*)d_in[14];
    const float* tok_w1  = (const float*)d_in[15];
    const float* tok_b1  = (const float*)d_in[16];
    const float* tok_w2  = (const float*)d_in[17];
    const float* tok_b2  = (const float*)d_in[18];

    const int N = in_sizes[0] / 128;   // 50000
    const int E = in_sizes[2] / 32;    // 400000
    const int* src = ei;
    const int* dst = ei + E;

    float *Hcat, *P, *M1, *U, *Eb, *T, *Xc, *Wc;
    cudaGetSymbolAddress((void**)&Hcat, g_Hcat);
    cudaGetSymbolAddress((void**)&P,    g_P);
    cudaGetSymbolAddress((void**)&M1,   g_M1);
    cudaGetSymbolAddress((void**)&U,    g_U);
    cudaGetSymbolAddress((void**)&Eb,   g_E);
    cudaGetSymbolAddress((void**)&T,    g_T);
    cudaGetSymbolAddress((void**)&Xc,   g_Xc);
    cudaGetSymbolAddress((void**)&Wc,   g_Wc);

    float* out_logits = (float*)d_out;
    float* out_h      = out_logits + N;

    const int mbN = (N + 127) / 128;   // 391
    const int mbE = (E + 127) / 128;   // 3125

    cudaFuncSetAttribute(tf32gemm<false, false, true,  true >, cudaFuncAttributeMaxDynamicSharedMemorySize, SMEM_BYTES);
    cudaFuncSetAttribute(tf32gemm<false, false, true,  false>, cudaFuncAttributeMaxDynamicSharedMemorySize, SMEM_BYTES);
    cudaFuncSetAttribute(tf32gemm<true,  true,  true,  false>, cudaFuncAttributeMaxDynamicSharedMemorySize, SMEM_BYTES);
    cudaFuncSetAttribute(tf32gemm<true,  false, false, true >, cudaFuncAttributeMaxDynamicSharedMemorySize, SMEM_BYTES);
    cudaFuncSetAttribute(tf32gemm<true,  false, true,  true >, cudaFuncAttributeMaxDynamicSharedMemorySize, SMEM_BYTES);
    cudaFuncSetAttribute(tf32gemm<true,  false, true,  false>, cudaFuncAttributeMaxDynamicSharedMemorySize, SMEM_BYTES);

    // ---- preamble: one kernel converts/repacks all weights + x ----
    cvt_all<<<CVT_ALL_BLOCKS, 256>>>(msg_w1, msg_w2, up_w1, up_w2,
                                     node_w, tok_w1, x, Wc, Xc);

    // h = x @ node_w + node_b -> Hcat[:, 0:256] (stored rounded)
    tf32gemm<false, false, true, true><<<dim3(2, mbN), 256, SMEM_BYTES>>>(
        Xc, 128, Wc + WC_NODE, 256, node_b, Hcat, 512, N, 128, nullptr);
    // e = edge_attr @ edge_w + edge_b
    edge_proj<<<(E + 7) / 8, 256>>>(ea, edge_w, edge_b, Eb, E);

    for (int l = 0; l < 3; l++) {
        // [Pa | Pb] = h @ Wab  (single N=512 GEMM, repacked weights)
        tf32gemm<false, false, true, false><<<dim3(4, mbN), 256, SMEM_BYTES>>>(
            Hcat, 512, Wc + WC_MSGAB + (size_t)l * 256 * 512, 512,
            nullptr, P, 512, N, 256, nullptr);
        // aggr = 0
        zero_aggr<<<(N * 64 + 255) / 256, 256>>>(Hcat, N);
        // hidden1 = rna(relu(Pa[dst] + Pb[src] + e@Wc + b1)) -> M1
        hidden1_kernel<<<(E + ET - 1) / ET, 256>>>(
            P, Eb, msg_w1 + (size_t)l * 544 * 256 + 512 * 256,
            msg_b1 + l * 256, src, dst, M1, E);
        // m = relu(M1 @ W2 + b2); aggr[dst] += m  (fused scatter)
        tf32gemm<true, true, true, false><<<dim3(2, mbE), 256, SMEM_BYTES>>>(
            M1, 256, Wc + WC_MSG2 + (size_t)l * 256 * 256, 256,
            msg_b2 + l * 256, Hcat + 256, 512, E, 256, dst);
        // u = relu([h|aggr] @ up_w1 + b1)  (A cvt-staged; U stored rounded)
        tf32gemm<true, false, false, true><<<dim3(2, mbN), 256, SMEM_BYTES>>>(
            Hcat, 512, Wc + WC_UP1 + (size_t)l * 512 * 256, 256,
            up_b1 + l * 256, U, 256, N, 512, nullptr);
        // h = relu(u @ up_w2 + b2) -> Hcat[:, 0:256] (stored rounded)
        tf32gemm<true, false, true, true><<<dim3(2, mbN), 256, SMEM_BYTES>>>(
            U, 256, Wc + WC_UP2 + (size_t)l * 256 * 256, 256,
            up_b2 + l * 256, Hcat, 512, N, 256, nullptr);
    }

    // token head
    tf32gemm<true, false, true, false><<<dim3(1, mbN), 256, SMEM_BYTES>>>(
        Hcat, 512, Wc + WC_TOK, 128, tok_b1, T, 128, N, 256, nullptr);
    head2<<<(N * 32 + 255) / 256, 256>>>(T, tok_w2, tok_b2, out_logits, N);
    copy_h<<<(N * 64 + 255) / 256, 256>>>(Hcat, out_h, N);
}

// round 10
// speedup vs baseline: 1.2569x; 1.0311x over previous
#include <cuda_runtime.h>
#include <cstdint>

// ---------------------------------------------------------------------------
// GNN message passing, 50000 nodes / 400000 edges / HIDDEN=256 / 3 layers.
// tf32 mma.sync.m16n8k8 GEMMs; BK=32 3-stage cp.async pipeline (barriers
// halved vs BK=16); ALL GEMM operands pre-rounded to tf32 (cvt fully hoisted:
// weights/x in preamble, M1/U/h at producers, aggr via cvt_aggr pass).
// PaPb merged (N=512, repacked Wab) + folds aggr zeroing into its epilogue.
// Segment-sum scatter fused into edge GEMM epilogue (red.global.add.v2.f32).
// R9 fix: cudaFuncSetAttribute now covers ALL five tf32gemm instantiations
// (the token-head variant was missing -> launch failure under graph capture).
// ---------------------------------------------------------------------------

#define NN 50000
#define NE 400000

__device__ float g_Hcat[(size_t)NN * 512];   // [h | aggr], h tf32-rounded
__device__ float g_P[(size_t)NN * 512];      // [Pa | Pb] (fp32)
__device__ float g_M1[(size_t)NE * 256];     // hidden1 per edge, tf32-rounded
__device__ float g_U[(size_t)NN * 256];      // update hidden, tf32-rounded
__device__ float g_E[(size_t)NE * 32];       // projected edge features
__device__ float g_T[(size_t)NN * 128];      // token head hidden
__device__ float g_Xc[(size_t)NN * 128];     // x, tf32-rounded
__device__ float g_Wc[1245184];              // all weights, tf32-rounded

// g_Wc offsets (floats)
#define WC_MSGAB 0                           // 3*256*512 (repacked W1ab)
#define WC_MSG2  393216                      // 3*256*256
#define WC_UP1   589824                      // 3*512*256
#define WC_UP2   983040                      // 3*256*256
#define WC_NODE  1179648                     // 128*256
#define WC_TOK   1212416                     // 256*128

__device__ __forceinline__ unsigned f2tf(float f) {
    unsigned u;
    asm("cvt.rna.tf32.f32 %0, %1;" : "=r"(u) : "f"(f));
    return u;
}
__device__ __forceinline__ float f2tf_f(float f) {
    return __uint_as_float(f2tf(f));
}
__device__ __forceinline__ uint32_t smem_u32(const void* p) {
    return (uint32_t)__cvta_generic_to_shared(p);
}
__device__ __forceinline__ void cp16(uint32_t dst, const void* src) {
    asm volatile("cp.async.cg.shared.global [%0], [%1], 16;" :: "r"(dst), "l"(src));
}
__device__ __forceinline__ void cp_commit() {
    asm volatile("cp.async.commit_group;" ::: "memory");
}

// smem layout (words): A bufs 3*4608 @0, B bufs 3*4352 @13824, bias 128 @26880
#define AW 36
#define ABUF 4608
#define BW 136
#define BBUF 4352
#define BOFF 13824
#define BIASOFF 26880
#define SMEM_BYTES ((BIASOFF + 128) * 4)     // 108032

// ---------------------------------------------------------------------------
// TF32 GEMM: C[M, gridDim.x*128] = act(A[M,K] @ B[K,N] + bias)
// 128x128 CTA tile, BK=32, 256 threads (8 warps, 32x64 each), 3-stage cp.async.
// A must be tf32-pre-rounded. K % 32 == 0.
// SCATTER: red.add.v2 into C[sidx[row]].  RSTORE: store tf32-rounded.
// zaux (optional, col0<256 blocks): zero zaux[r*ldc + col0 + ...] rows (aggr).
// ---------------------------------------------------------------------------
template <bool RELU, bool SCATTER, bool RSTORE>
__global__ __launch_bounds__(256, 2) void tf32gemm(
    const float* __restrict__ A, int lda,
    const float* __restrict__ B, int ldb,
    const float* __restrict__ bias,
    float* __restrict__ C, int ldc,
    int M, int K,
    const int* __restrict__ sidx,
    float* __restrict__ zaux)
{
    extern __shared__ unsigned dynsmem[];

    const int tid  = threadIdx.x;
    const int lane = tid & 31;
    const int wid  = tid >> 5;
    const int warpRow = wid >> 1;
    const int warpCol = wid & 1;
    const int qr = lane >> 2;
    const int qk = lane & 3;

    const int row0 = blockIdx.y * 128;
    const int col0 = blockIdx.x * 128;

    const int bK  = tid >> 5;    // 0..7
    const int bC4 = tid & 31;

    float* sbias = (float*)(dynsmem + BIASOFF);
    if (tid < 128) sbias[tid] = bias ? bias[col0 + tid] : 0.f;

    const int nc = K >> 5;

    auto cpA = [&](int s, int k0) {
        unsigned* buf = dynsmem + (s % 3) * ABUF;
#pragma unroll
        for (int i = 0; i < 4; i++) {
            int idx = tid + i * 256;        // 0..1023
            int row = idx >> 3;             // 0..127
            int c4  = idx & 7;              // 0..7
            int gr  = min(row0 + row, M - 1);
            cp16(smem_u32(&buf[row * AW + c4 * 4]),
                 A + (size_t)gr * lda + k0 + c4 * 4);
        }
    };
    auto cpB = [&](int s, int k0) {
        unsigned* buf = dynsmem + BOFF + (s % 3) * BBUF;
#pragma unroll
        for (int u = 0; u < 4; u++) {
            int k = bK + u * 8;             // 0..31
            cp16(smem_u32(&buf[k * BW + bC4 * 4]),
                 B + (size_t)(k0 + k) * ldb + col0 + bC4 * 4);
        }
    };

    cpA(0, 0);  cpB(0, 0);  cp_commit();
    if (nc > 1) { cpA(1, 32); cpB(1, 32); cp_commit(); }

    float acc[2][8][4];
#pragma unroll
    for (int i = 0; i < 2; i++)
#pragma unroll
        for (int j = 0; j < 8; j++)
#pragma unroll
            for (int c = 0; c < 4; c++) acc[i][j][c] = 0.f;

    const int mbase = warpRow * 32;
    const int nbase = warpCol * 64;

    for (int s = 0; s < nc; s++) {
        if (s + 1 < nc)
            asm volatile("cp.async.wait_group 1;" ::: "memory");
        else
            asm volatile("cp.async.wait_group 0;" ::: "memory");
        __syncthreads();

        if (s + 2 < nc) {
            cpA(s + 2, (s + 2) << 5);
            cpB(s + 2, (s + 2) << 5);
            cp_commit();
        }

        const unsigned* As = dynsmem + (s % 3) * ABUF;
        const unsigned* Bs = dynsmem + BOFF + (s % 3) * BBUF;

#pragma unroll
        for (int kk = 0; kk < 32; kk += 8) {
            unsigned a[2][4], b[8][2];
#pragma unroll
            for (int i = 0; i < 2; i++) {
                int r = mbase + i * 16 + qr;
                a[i][0] = As[r * AW + kk + qk];
                a[i][1] = As[(r + 8) * AW + kk + qk];
                a[i][2] = As[r * AW + kk + 4 + qk];
                a[i][3] = As[(r + 8) * AW + kk + 4 + qk];
            }
#pragma unroll
            for (int j = 0; j < 8; j++) {
                int c = nbase + j * 8 + qr;
                b[j][0] = Bs[(kk + qk) * BW + c];
                b[j][1] = Bs[(kk + 4 + qk) * BW + c];
            }
#pragma unroll
            for (int i = 0; i < 2; i++)
#pragma unroll
                for (int j = 0; j < 8; j++) {
                    asm volatile(
                        "mma.sync.aligned.m16n8k8.row.col.f32.tf32.tf32.f32 "
                        "{%0,%1,%2,%3}, {%4,%5,%6,%7}, {%8,%9}, {%0,%1,%2,%3};"
                        : "+f"(acc[i][j][0]), "+f"(acc[i][j][1]),
                          "+f"(acc[i][j][2]), "+f"(acc[i][j][3])
                        : "r"(a[i][0]), "r"(a[i][1]), "r"(a[i][2]), "r"(a[i][3]),
                          "r"(b[j][0]), "r"(b[j][1]));
                }
        }
    }

    // ---- epilogue ----
#pragma unroll
    for (int i = 0; i < 2; i++) {
#pragma unroll
        for (int h = 0; h < 2; h++) {
            int r = row0 + mbase + i * 16 + qr + h * 8;
            if (r >= M) continue;
            if (SCATTER) {
                int target = sidx[r];
                float* Crow = C + (size_t)target * ldc;
#pragma unroll
                for (int j = 0; j < 8; j++) {
                    int c = col0 + nbase + j * 8 + 2 * qk;
                    float v0 = acc[i][j][h * 2 + 0] + sbias[c - col0];
                    float v1 = acc[i][j][h * 2 + 1] + sbias[c - col0 + 1];
                    if (RELU) { v0 = fmaxf(v0, 0.f); v1 = fmaxf(v1, 0.f); }
                    asm volatile("red.global.add.v2.f32 [%0], {%1, %2};"
                                 :: "l"(Crow + c), "f"(v0), "f"(v1) : "memory");
                }
            } else {
                float* Crow = C + (size_t)r * ldc;
#pragma unroll
                for (int j = 0; j < 8; j++) {
                    int c = col0 + nbase + j * 8 + 2 * qk;
                    float v0 = acc[i][j][h * 2 + 0] + sbias[c - col0];
                    float v1 = acc[i][j][h * 2 + 1] + sbias[c - col0 + 1];
                    if (RELU) { v0 = fmaxf(v0, 0.f); v1 = fmaxf(v1, 0.f); }
                    if (RSTORE) { v0 = f2tf_f(v0); v1 = f2tf_f(v1); }
                    *(float2*)(Crow + c) = make_float2(v0, v1);
                }
                if (zaux != nullptr && col0 < 256) {
                    float* Zrow = zaux + (size_t)r * ldc;
#pragma unroll
                    for (int j = 0; j < 8; j++) {
                        int c = col0 + nbase + j * 8 + 2 * qk;
                        *(float2*)(Zrow + c) = make_float2(0.f, 0.f);
                    }
                }
            }
        }
    }
}

// ---------------------------------------------------------------------------
// One-shot preamble: tf32-round all weights + x; repack msg_w1[0:512] into
// Wab[256][512].
// ---------------------------------------------------------------------------
__global__ __launch_bounds__(256) void cvt_all(
    const float* __restrict__ msg_w1, const float* __restrict__ msg_w2,
    const float* __restrict__ up_w1,  const float* __restrict__ up_w2,
    const float* __restrict__ node_w, const float* __restrict__ tok_w1,
    const float* __restrict__ x,
    float* __restrict__ Wc, float* __restrict__ Xc)
{
    const int b = blockIdx.x;
    const int t = threadIdx.x;
    const float* src;
    float* dst;
    int i4;
    if (b < 384) {                       // repack Wab: 3*256*512/4 f4
        i4 = b * 256 + t;
        int l   = i4 >> 15;
        int rem = i4 & 32767;
        int k   = rem >> 7;
        int n   = (rem & 127) << 2;
        src = (n < 256)
            ? msg_w1 + (size_t)l * 544 * 256 + (size_t)k * 256 + n
            : msg_w1 + (size_t)l * 544 * 256 + (size_t)(256 + k) * 256 + (n - 256);
        dst = Wc + WC_MSGAB + (size_t)i4 * 4;
    } else if (b < 576) {
        i4 = (b - 384) * 256 + t;
        src = msg_w2 + (size_t)i4 * 4; dst = Wc + WC_MSG2 + (size_t)i4 * 4;
    } else if (b < 960) {
        i4 = (b - 576) * 256 + t;
        src = up_w1 + (size_t)i4 * 4;  dst = Wc + WC_UP1 + (size_t)i4 * 4;
    } else if (b < 1152) {
        i4 = (b - 960) * 256 + t;
        src = up_w2 + (size_t)i4 * 4;  dst = Wc + WC_UP2 + (size_t)i4 * 4;
    } else if (b < 1184) {
        i4 = (b - 1152) * 256 + t;
        src = node_w + (size_t)i4 * 4; dst = Wc + WC_NODE + (size_t)i4 * 4;
    } else if (b < 1216) {
        i4 = (b - 1184) * 256 + t;
        src = tok_w1 + (size_t)i4 * 4; dst = Wc + WC_TOK + (size_t)i4 * 4;
    } else {
        i4 = (b - 1216) * 256 + t;
        src = x + (size_t)i4 * 4;      dst = Xc + (size_t)i4 * 4;
    }
    float4 v = *(const float4*)src;
    float4 o = { f2tf_f(v.x), f2tf_f(v.y), f2tf_f(v.z), f2tf_f(v.w) };
    *(float4*)dst = o;
}
#define CVT_ALL_BLOCKS (1216 + 6250)

// round aggr half of Hcat in place (post-scatter, pre-up1)
__global__ void cvt_aggr(float* __restrict__ Hcat, int N)
{
    int idx = blockIdx.x * blockDim.x + threadIdx.x;
    if (idx < N * 64) {
        int r = idx >> 6, c = (idx & 63) << 2;
        float4* p = (float4*)(Hcat + (size_t)r * 512 + 256 + c);
        float4 v = *p;
        float4 o = { f2tf_f(v.x), f2tf_f(v.y), f2tf_f(v.z), f2tf_f(v.w) };
        *p = o;
    }
}

// ---------------------------------------------------------------------------
// hidden1[e, :] = rna(relu( Pa[dst[e]] + Pb[src[e]] + ebuf[e]·Wc + b1 ))
// ---------------------------------------------------------------------------
#define ET 16
__global__ __launch_bounds__(256) void hidden1_kernel(
    const float* __restrict__ P,
    const float* __restrict__ Ebuf,
    const float* __restrict__ Wc,
    const float* __restrict__ b1,
    const int* __restrict__ src,
    const int* __restrict__ dst,
    float* __restrict__ out,
    int E)
{
    const int j = threadIdx.x;
    const int e0 = blockIdx.x * ET;
    __shared__ float esm[ET][32];
    __shared__ int sdst[ET], ssrc[ET];

    float wc[32];
#pragma unroll
    for (int k = 0; k < 32; k++) wc[k] = Wc[k * 256 + j];

    const int ne = min(ET, E - e0);
    if (j < ne) {
        sdst[j] = dst[e0 + j];
        ssrc[j] = src[e0 + j];
    }
    for (int t = j; t < ne * 32; t += 256)
        esm[t >> 5][t & 31] = Ebuf[(size_t)e0 * 32 + t];
    __syncthreads();

    const float bj = b1[j];
    for (int i = 0; i < ne; i++) {
        float acc = bj + P[(size_t)sdst[i] * 512 + j]
                       + P[(size_t)ssrc[i] * 512 + 256 + j];
#pragma unroll
        for (int k = 0; k < 32; k++) acc = fmaf(esm[i][k], wc[k], acc);
        out[(size_t)(e0 + i) * 256 + j] = f2tf_f(fmaxf(acc, 0.f));
    }
}

// ---------------------------------------------------------------------------
__global__ __launch_bounds__(256) void edge_proj(
    const float* __restrict__ ea, const float* __restrict__ W,
    const float* __restrict__ b, float* __restrict__ out, int E)
{
    __shared__ float Ws[1024];
    __shared__ float es[8][32];
    const int t = threadIdx.x;
    for (int i = t; i < 1024; i += 256) Ws[i] = W[i];
    const int e0 = blockIdx.x * 8;
    const int ne = min(8, E - e0);
    for (int i = t; i < ne * 32; i += 256)
        es[i >> 5][i & 31] = ea[(size_t)e0 * 32 + i];
    __syncthreads();
    const int el = t >> 5, c = t & 31;
    if (el < ne) {
        float acc = b[c];
#pragma unroll
        for (int k = 0; k < 32; k++) acc = fmaf(es[el][k], Ws[k * 32 + c], acc);
        out[(size_t)(e0 + el) * 32 + c] = acc;
    }
}

__global__ void head2(const float* __restrict__ T, const float* __restrict__ w2,
                      const float* __restrict__ b2, float* __restrict__ out, int N)
{
    int gw = (blockIdx.x * blockDim.x + threadIdx.x) >> 5;
    int lane = threadIdx.x & 31;
    if (gw >= N) return;
    const float* row = T + (size_t)gw * 128;
    float s = 0.f;
#pragma unroll
    for (int k = lane; k < 128; k += 32) s = fmaf(row[k], w2[k], s);
#pragma unroll
    for (int o = 16; o; o >>= 1) s += __shfl_xor_sync(0xFFFFFFFFu, s, o);
    if (lane == 0) out[gw] = s + b2[0];
}

__global__ void copy_h(const float* __restrict__ Hcat, float* __restrict__ out, int N)
{
    int idx = blockIdx.x * blockDim.x + threadIdx.x;
    if (idx < N * 64) {
        int r = idx >> 6, c = (idx & 63) << 2;
        *(float4*)(out + (size_t)r * 256 + c) =
            *(const float4*)(Hcat + (size_t)r * 512 + c);
    }
}

// ---------------------------------------------------------------------------
extern "C" void kernel_launch(void* const* d_in, const int* in_sizes, int n_in,
                              void* d_out, int out_size)
{
    const float* x       = (const float*)d_in[0];
    const int*   ei      = (const int*)d_in[1];
    const float* ea      = (const float*)d_in[2];
    const float* node_w  = (const float*)d_in[3];
    const float* node_b  = (const float*)d_in[4];
    const float* edge_w  = (const float*)d_in[5];
    const float* edge_b  = (const float*)d_in[6];
    const float* msg_w1  = (const float*)d_in[7];
    const float* msg_b1  = (const float*)d_in[8];
    const float* msg_w2  = (const float*)d_in[9];
    const float* msg_b2  = (const float*)d_in[10];
    const float* up_w1   = (const float*)d_in[11];
    const float* up_b1   = (const float*)d_in[12];
    const float* up_w2   = (const float*)d_in[13];
    const float* up_b2   = (const float*)d_in[14];
    const float* tok_w1  = (const float*)d_in[15];
    const float* tok_b1  = (const float*)d_in[16];
    const float* tok_w2  = (const float*)d_in[17];
    const float* tok_b2  = (const float*)d_in[18];

    const int N = in_sizes[0] / 128;   // 50000
    const int E = in_sizes[2] / 32;    // 400000
    const int* src = ei;
    const int* dst = ei + E;

    float *Hcat, *P, *M1, *U, *Eb, *T, *Xc, *Wc;
    cudaGetSymbolAddress((void**)&Hcat, g_Hcat);
    cudaGetSymbolAddress((void**)&P,    g_P);
    cudaGetSymbolAddress((void**)&M1,   g_M1);
    cudaGetSymbolAddress((void**)&U,    g_U);
    cudaGetSymbolAddress((void**)&Eb,   g_E);
    cudaGetSymbolAddress((void**)&T,    g_T);
    cudaGetSymbolAddress((void**)&Xc,   g_Xc);
    cudaGetSymbolAddress((void**)&Wc,   g_Wc);

    float* out_logits = (float*)d_out;
    float* out_h      = out_logits + N;

    const int mbN = (N + 127) / 128;   // 391
    const int mbE = (E + 127) / 128;   // 3125

    // ALL five instantiations used below must be listed here (R9 bug: the
    // token-head <true,false,false> variant was missing -> launch failure).
    cudaFuncSetAttribute(tf32gemm<false, false, true >, cudaFuncAttributeMaxDynamicSharedMemorySize, SMEM_BYTES);
    cudaFuncSetAttribute(tf32gemm<false, false, false>, cudaFuncAttributeMaxDynamicSharedMemorySize, SMEM_BYTES);
    cudaFuncSetAttribute(tf32gemm<true,  true,  false>, cudaFuncAttributeMaxDynamicSharedMemorySize, SMEM_BYTES);
    cudaFuncSetAttribute(tf32gemm<true,  false, true >, cudaFuncAttributeMaxDynamicSharedMemorySize, SMEM_BYTES);
    cudaFuncSetAttribute(tf32gemm<true,  false, false>, cudaFuncAttributeMaxDynamicSharedMemorySize, SMEM_BYTES);

    // ---- preamble: convert/repack all weights + x ----
    cvt_all<<<CVT_ALL_BLOCKS, 256>>>(msg_w1, msg_w2, up_w1, up_w2,
                                     node_w, tok_w1, x, Wc, Xc);

    // h = x @ node_w + node_b -> Hcat[:, 0:256] (stored rounded)
    tf32gemm<false, false, true><<<dim3(2, mbN), 256, SMEM_BYTES>>>(
        Xc, 128, Wc + WC_NODE, 256, node_b, Hcat, 512, N, 128, nullptr, nullptr);
    // e = edge_attr @ edge_w + edge_b
    edge_proj<<<(E + 7) / 8, 256>>>(ea, edge_w, edge_b, Eb, E);

    for (int l = 0; l < 3; l++) {
        // [Pa | Pb] = h @ Wab; col0<256 blocks also zero the aggr half
        tf32gemm<false, false, false><<<dim3(4, mbN), 256, SMEM_BYTES>>>(
            Hcat, 512, Wc + WC_MSGAB + (size_t)l * 256 * 512, 512,
            nullptr, P, 512, N, 256, nullptr, Hcat + 256);
        // hidden1 = rna(relu(Pa[dst] + Pb[src] + e@Wc + b1)) -> M1
        hidden1_kernel<<<(E + ET - 1) / ET, 256>>>(
            P, Eb, msg_w1 + (size_t)l * 544 * 256 + 512 * 256,
            msg_b1 + l * 256, src, dst, M1, E);
        // m = relu(M1 @ W2 + b2); aggr[dst] += m  (fused scatter)
        tf32gemm<true, true, false><<<dim3(2, mbE), 256, SMEM_BYTES>>>(
            M1, 256, Wc + WC_MSG2 + (size_t)l * 256 * 256, 256,
            msg_b2 + l * 256, Hcat + 256, 512, E, 256, dst, nullptr);
        // round aggr in place (same rna the old cvt-staging applied)
        cvt_aggr<<<(N * 64 + 255) / 256, 256>>>(Hcat, N);
        // u = relu([h|aggr] @ up_w1 + b1)  (all-tf32 A now)
        tf32gemm<true, false, true><<<dim3(2, mbN), 256, SMEM_BYTES>>>(
            Hcat, 512, Wc + WC_UP1 + (size_t)l * 512 * 256, 256,
            up_b1 + l * 256, U, 256, N, 512, nullptr, nullptr);
        // h = relu(u @ up_w2 + b2) -> Hcat[:, 0:256] (stored rounded)
        tf32gemm<true, false, true><<<dim3(2, mbN), 256, SMEM_BYTES>>>(
            U, 256, Wc + WC_UP2 + (size_t)l * 256 * 256, 256,
            up_b2 + l * 256, Hcat, 512, N, 256, nullptr, nullptr);
    }

    // token head
    tf32gemm<true, false, false><<<dim3(1, mbN), 256, SMEM_BYTES>>>(
        Hcat, 512, Wc + WC_TOK, 128, tok_b1, T, 128, N, 256, nullptr, nullptr);
    head2<<<(N * 32 + 255) / 256, 256>>>(T, tok_w2, tok_b2, out_logits, N);
    copy_h<<<(N * 64 + 255) / 256, 256>>>(Hcat, out_h, N);
}